// round 2
// baseline (speedup 1.0000x reference)
#include <cuda_runtime.h>

// FilterLayer: y[b,c,h,w] = sum_{i,j in 5x5} x_pad[b,c,h+i,w+j] * f[b,i*5+j,h,w]
// B=4, C=3, H=W=512, window=5, zero padding of 2.
// HBM-bound: f (105MB) dominates, streamed with __ldcs (evict-first) so the
// x image (12.6MB, reused 25x) stays L2-resident. x staged in smem,
// conflict-free stride-1 LDS.

#define IMG_H 512
#define IMG_W 512
#define TW 32
#define TH 8
#define HALO 2
#define TILE_R (TH + 2 * HALO)   // 12
#define TILE_C (TW + 2 * HALO)   // 36

__global__ __launch_bounds__(256, 8)
void filter_layer_kernel(const float* __restrict__ x,
                         const float* __restrict__ f,
                         float* __restrict__ out)
{
    __shared__ float xs[3][TILE_R][TILE_C];

    const int b  = blockIdx.z;
    const int w0 = blockIdx.x * TW;
    const int h0 = blockIdx.y * TH;
    const int tx = threadIdx.x;
    const int ty = threadIdx.y;
    const int tid = ty * TW + tx;

    const int HW = IMG_H * IMG_W;

    // ---- Stage 3-channel x tile with halo (zero-padded at borders) ----
    const float* xb = x + (size_t)b * 3 * HW;
    #pragma unroll
    for (int idx = tid; idx < 3 * TILE_R * TILE_C; idx += 256) {
        int c   = idx / (TILE_R * TILE_C);
        int rem = idx - c * (TILE_R * TILE_C);
        int r   = rem / TILE_C;
        int col = rem - r * TILE_C;
        int gr  = h0 + r - HALO;
        int gc  = w0 + col - HALO;
        float v = 0.0f;
        if ((unsigned)gr < (unsigned)IMG_H && (unsigned)gc < (unsigned)IMG_W)
            v = __ldg(xb + c * HW + gr * IMG_W + gc);
        xs[c][r][col] = v;
    }
    __syncthreads();

    // ---- Per-pixel 25-tap weighted sum, f value shared across 3 channels ----
    const int h = h0 + ty;
    const int w = w0 + tx;
    const float* fp = f + (size_t)b * 25 * HW + h * IMG_W + w;

    float a0 = 0.0f, a1 = 0.0f, a2 = 0.0f;
    #pragma unroll
    for (int k = 0; k < 25; ++k) {
        const int i = k / 5;
        const int j = k % 5;
        // streaming load: f is touched exactly once -> evict-first policy
        const float fv = __ldcs(fp + (size_t)k * HW);
        a0 = fmaf(xs[0][ty + i][tx + j], fv, a0);
        a1 = fmaf(xs[1][ty + i][tx + j], fv, a1);
        a2 = fmaf(xs[2][ty + i][tx + j], fv, a2);
    }

    float* op = out + (size_t)b * 3 * HW + h * IMG_W + w;
    op[0]              = a0;
    op[(size_t)HW]     = a1;
    op[(size_t)2 * HW] = a2;
}

extern "C" void kernel_launch(void* const* d_in, const int* in_sizes, int n_in,
                              void* d_out, int out_size)
{
    const float* x = (const float*)d_in[0];
    const float* f = (const float*)d_in[1];
    float* out = (float*)d_out;

    dim3 block(TW, TH, 1);                       // 256 threads
    dim3 grid(IMG_W / TW, IMG_H / TH, 4);        // 16 x 64 x 4
    filter_layer_kernel<<<grid, block>>>(x, f, out);
}